// round 14
// baseline (speedup 1.0000x reference)
#include <cuda_runtime.h>
#include <cuda_bf16.h>
#include <cstdint>

// GRU sequence encoder, round 14: HMMA recurrence, per-dim-tile restructure.
// N=16384, L=512, ES=32, HS=64, gates [r|z|n] (torch order).
//
// Each warp owns 16 length-sorted seqs (no CTA-wide sync in the loop).
// Per step, per dim-tile d (8 dims): 3 gate n-tiles (r,z,n) = 36 HMMA
// m16n8k16 bf16 (split precision, 3 terms), then immediate epilogue for
// those dims -> accumulator live range 12 regs (was 96; R13 spilled at 255).
// 128-thread CTAs, 3 CTAs/SM target.

#define N_SEQ   16384
#define L_SEQ   512
#define ES_DIM  32
#define HS_DIM  64
#define G3      192
#define NGROUP  (N_SEQ / 16)   // 1024
#define NBUCKET 513
#define VOCAB   32000
#define WROW    72             // padded bf16 row stride (144 B)

__device__ float P[(size_t)VOCAB * G3];   // e.w_ih^T + b_ih (+b_hh for r,z)
__device__ int d_len[N_SEQ];
__device__ int d_bucket[NBUCKET];
__device__ int d_off[NBUCKET];
__device__ int d_sorted[N_SEQ];

// ---------------- PTX helpers ----------------

__device__ __forceinline__ uint32_t smem_to_u32(const void* p) {
    uint32_t a;
    asm("{ .reg .u64 t; cvta.to.shared.u64 t, %1; cvt.u32.u64 %0, t; }"
        : "=r"(a) : "l"(p));
    return a;
}

#define LDSM_X2(r, addr) \
    asm volatile("ldmatrix.sync.aligned.m8n8.x2.shared.b16 {%0,%1}, [%2];" \
                 : "=r"((r)[0]), "=r"((r)[1]) : "r"(addr))

#define MMA_BF16(c, a, b) \
    asm volatile("mma.sync.aligned.m16n8k16.row.col.f32.bf16.bf16.f32 " \
                 "{%0,%1,%2,%3}, {%4,%5,%6,%7}, {%8,%9}, {%0,%1,%2,%3};" \
                 : "+f"((c)[0]), "+f"((c)[1]), "+f"((c)[2]), "+f"((c)[3]) \
                 : "r"((a)[0]), "r"((a)[1]), "r"((a)[2]), "r"((a)[3]), \
                   "r"((b)[0]), "r"((b)[1]))

// one n-tile (8 gate rows): 12 HMMA (3 split-precision terms)
__device__ __forceinline__ void mma_ntile(float acc[4],
                                          uint32_t addr_hi, uint32_t addr_lo,
                                          const uint32_t Ahi[4][4],
                                          const uint32_t Alo[4][4])
{
    uint32_t bh[4][2], bl[4][2];
    #pragma unroll
    for (int k = 0; k < 4; k++) {
        LDSM_X2(bh[k], addr_hi + 32 * k);
        LDSM_X2(bl[k], addr_lo + 32 * k);
    }
    #pragma unroll
    for (int k = 0; k < 4; k++) MMA_BF16(acc, Ahi[k], bh[k]);
    #pragma unroll
    for (int k = 0; k < 4; k++) MMA_BF16(acc, Alo[k], bh[k]);
    #pragma unroll
    for (int k = 0; k < 4; k++) MMA_BF16(acc, Ahi[k], bl[k]);
}

// ---------------- prepass ----------------

__global__ void zero_kernel() {
    int t = threadIdx.x;
    if (t < NBUCKET) d_bucket[t] = 0;
}

#define LEN_CTAS 2048
#define P_ROWS_PER_CTA 64

__global__ void len_pre_kernel(const int* __restrict__ x,
                               const float* __restrict__ emb,
                               const float* __restrict__ w_ih,
                               const float* __restrict__ b_ih,
                               const float* __restrict__ b_hh)
{
    if (blockIdx.x < LEN_CTAS) {
        int seq  = blockIdx.x * 8 + (threadIdx.x >> 5);
        int lane = threadIdx.x & 31;
        const int4* row = reinterpret_cast<const int4*>(x + (long)seq * L_SEQ);
        int c = 0;
        #pragma unroll
        for (int k = 0; k < 4; k++) {
            int4 v = row[lane + 32 * k];
            c += (v.x != 0) + (v.y != 0) + (v.z != 0) + (v.w != 0);
        }
        #pragma unroll
        for (int off = 16; off > 0; off >>= 1) c += __shfl_xor_sync(~0u, c, off);
        if (lane == 0) {
            d_len[seq] = c;
            atomicAdd(&d_bucket[c], 1);
        }
    } else {
        int j = threadIdx.x;
        if (j >= G3) return;
        float w[ES_DIM];
        {
            const float4* wr = reinterpret_cast<const float4*>(w_ih + (long)j * ES_DIM);
            #pragma unroll
            for (int k = 0; k < ES_DIM / 4; k++) {
                float4 v = wr[k];
                w[4*k+0] = v.x; w[4*k+1] = v.y; w[4*k+2] = v.z; w[4*k+3] = v.w;
            }
        }
        const float bj = b_ih[j] + ((j < 128) ? b_hh[j] : 0.0f);
        int v0 = (blockIdx.x - LEN_CTAS) * P_ROWS_PER_CTA;
        for (int v = v0; v < v0 + P_ROWS_PER_CTA && v < VOCAB; v++) {
            const float4* er = reinterpret_cast<const float4*>(emb + (long)v * ES_DIM);
            float acc = bj;
            #pragma unroll
            for (int k = 0; k < ES_DIM / 4; k++) {
                float4 e = __ldg(&er[k]);
                acc = fmaf(w[4*k+0], e.x, acc);
                acc = fmaf(w[4*k+1], e.y, acc);
                acc = fmaf(w[4*k+2], e.z, acc);
                acc = fmaf(w[4*k+3], e.w, acc);
            }
            P[(size_t)v * G3 + j] = acc;
        }
    }
}

__global__ void scan_scatter_kernel() {
    __shared__ int sb[NBUCKET], so[NBUCKET];
    int t = threadIdx.x;
    for (int i = t; i < NBUCKET; i += blockDim.x) sb[i] = d_bucket[i];
    __syncthreads();
    if (t == 0) {
        int run = 0;
        for (int l = NBUCKET - 1; l >= 0; l--) { so[l] = run; run += sb[l]; }
    }
    __syncthreads();
    for (int i = t; i < NBUCKET; i += blockDim.x) d_off[i] = so[i];
    __syncthreads();
    for (int seq = t; seq < N_SEQ; seq += blockDim.x) {
        int l = d_len[seq];
        int pos = atomicAdd(&d_off[l], 1);
        d_sorted[pos] = seq;
    }
}

// ---------------- main ----------------

#define SMEM_SZ (2 * G3 * WROW * 2)   // 55296 B: w_hi + w_lo

__global__ void __launch_bounds__(128, 3)
gru_mma(const int* __restrict__ x, const float* __restrict__ w_hh,
        const float* __restrict__ b_hh, float* __restrict__ out)
{
    extern __shared__ __align__(16) char smem[];
    __nv_bfloat16* whi = reinterpret_cast<__nv_bfloat16*>(smem);
    __nv_bfloat16* wlo = whi + G3 * WROW;

    const int tid = threadIdx.x;

    for (int idx = tid; idx < G3 * HS_DIM; idx += 128) {
        int r = idx >> 6, k = idx & 63;
        float w = w_hh[(long)r * HS_DIM + k];
        __nv_bfloat16 hi = __float2bfloat16(w);
        whi[r * WROW + k] = hi;
        wlo[r * WROW + k] = __float2bfloat16(w - __bfloat162float(hi));
    }
    __syncthreads();

    const int wid  = tid >> 5;
    const int lane = tid & 31;
    const int grp  = blockIdx.x * 4 + wid;

    const int g  = lane >> 2;    // owns seqs g, g+8 of the group
    const int t4 = lane & 3;     // cols 2*t4, 2*t4+1 per 8-wide n-tile

    const int base = grp * 16;
    const int seqA = d_sorted[base + g];
    const int seqB = d_sorted[base + g + 8];
    const int lenA = d_len[seqA];
    const int lenB = d_len[seqB];
    const int maxlen = d_len[d_sorted[base]];   // descending sort

    const uint32_t whi_u = smem_to_u32(whi);
    const uint32_t wlo_u = smem_to_u32(wlo);
    const uint32_t laddr = (uint32_t)((lane & 7) * (WROW * 2) + ((lane >> 3) & 1) * 16);

    float hA[16], hB[16];
    uint32_t Ahi[4][4], Alo[4][4];
    #pragma unroll
    for (int i = 0; i < 16; i++) { hA[i] = 0.f; hB[i] = 0.f; }
    #pragma unroll
    for (int k = 0; k < 4; k++)
        #pragma unroll
        for (int i = 0; i < 4; i++) { Ahi[k][i] = 0u; Alo[k][i] = 0u; }

    const int* xA = x + (size_t)seqA * L_SEQ;
    const int* xB = x + (size_t)seqB * L_SEQ;
    int tokA = __ldg(xA);
    int tokB = __ldg(xB);

    for (int t = 0; t < maxlen; t++) {
        const int tn = (t + 1 < L_SEQ) ? t + 1 : t;
        const int tokA_n = __ldg(xA + tn);
        const int tokB_n = __ldg(xB + tn);

        const float* pA = P + (size_t)tokA * G3;
        const float* pB = P + (size_t)tokB * G3;
        const bool liveA = (t < lenA);
        const bool liveB = (t < lenB);

        // ---- per dim-tile: 36 HMMA then immediate epilogue ----
        #pragma unroll
        for (int d = 0; d < 8; d++) {
            float accR[4] = {0.f, 0.f, 0.f, 0.f};
            float accZ[4] = {0.f, 0.f, 0.f, 0.f};
            float accN[4] = {0.f, 0.f, 0.f, 0.f};
            uint32_t roR = (uint32_t)(8 * d) * (WROW * 2) + laddr;
            uint32_t roZ = (uint32_t)(64 + 8 * d) * (WROW * 2) + laddr;
            uint32_t roN = (uint32_t)(128 + 8 * d) * (WROW * 2) + laddr;
            mma_ntile(accR, whi_u + roR, wlo_u + roR, Ahi, Alo);
            mma_ntile(accZ, whi_u + roZ, wlo_u + roZ, Ahi, Alo);
            mma_ntile(accN, whi_u + roN, wlo_u + roN, Ahi, Alo);

            const int c0 = 8 * d + 2 * t4;
            float2 gxrA = __ldg(reinterpret_cast<const float2*>(pA + c0));
            float2 gxzA = __ldg(reinterpret_cast<const float2*>(pA + 64 + c0));
            float2 gxnA = __ldg(reinterpret_cast<const float2*>(pA + 128 + c0));
            float2 gxrB = __ldg(reinterpret_cast<const float2*>(pB + c0));
            float2 gxzB = __ldg(reinterpret_cast<const float2*>(pB + 64 + c0));
            float2 gxnB = __ldg(reinterpret_cast<const float2*>(pB + 128 + c0));
            float2 bnn  = __ldg(reinterpret_cast<const float2*>(b_hh + 128 + c0));

            #pragma unroll
            for (int i = 0; i < 2; i++) {
                float bn = i ? bnn.y : bnn.x;

                float prA = (i ? gxrA.y : gxrA.x) + accR[i];
                float pzA = (i ? gxzA.y : gxzA.x) + accZ[i];
                float xnA = (i ? gxnA.y : gxnA.x);
                float hnA = accN[i] + bn;
                float rA = __fdividef(1.0f, 1.0f + __expf(-prA));
                float zA = __fdividef(1.0f, 1.0f + __expf(-pzA));
                float aA = fmaf(rA, hnA, xnA);
                float nA = 1.0f - __fdividef(2.0f, __expf(2.0f * aA) + 1.0f);
                float hoA = hA[2 * d + i];
                hA[2 * d + i] = liveA ? fmaf(zA, hoA - nA, nA) : hoA;

                float prB = (i ? gxrB.y : gxrB.x) + accR[2 + i];
                float pzB = (i ? gxzB.y : gxzB.x) + accZ[2 + i];
                float xnB = (i ? gxnB.y : gxnB.x);
                float hnB = accN[2 + i] + bn;
                float rB = __fdividef(1.0f, 1.0f + __expf(-prB));
                float zB = __fdividef(1.0f, 1.0f + __expf(-pzB));
                float aB = fmaf(rB, hnB, xnB);
                float nB = 1.0f - __fdividef(2.0f, __expf(2.0f * aB) + 1.0f);
                float hoB = hB[2 * d + i];
                hB[2 * d + i] = liveB ? fmaf(zB, hoB - nB, nB) : hoB;
            }
        }
        tokA = tokA_n;
        tokB = tokB_n;

        // ---- repack h into next step's A fragments (registers only) ----
        #pragma unroll
        for (int k = 0; k < 4; k++) {
            float a0l = hA[4 * k],     a0h = hA[4 * k + 1];
            float a1l = hB[4 * k],     a1h = hB[4 * k + 1];
            float a2l = hA[4 * k + 2], a2h = hA[4 * k + 3];
            float a3l = hB[4 * k + 2], a3h = hB[4 * k + 3];
            uint32_t p0, p1, p2, p3;
            asm("cvt.rn.bf16x2.f32 %0, %1, %2;" : "=r"(p0) : "f"(a0h), "f"(a0l));
            asm("cvt.rn.bf16x2.f32 %0, %1, %2;" : "=r"(p1) : "f"(a1h), "f"(a1l));
            asm("cvt.rn.bf16x2.f32 %0, %1, %2;" : "=r"(p2) : "f"(a2h), "f"(a2l));
            asm("cvt.rn.bf16x2.f32 %0, %1, %2;" : "=r"(p3) : "f"(a3h), "f"(a3l));
            Ahi[k][0] = p0; Ahi[k][1] = p1; Ahi[k][2] = p2; Ahi[k][3] = p3;
            float r0l = a0l - __uint_as_float(p0 << 16);
            float r0h = a0h - __uint_as_float(p0 & 0xffff0000u);
            float r1l = a1l - __uint_as_float(p1 << 16);
            float r1h = a1h - __uint_as_float(p1 & 0xffff0000u);
            float r2l = a2l - __uint_as_float(p2 << 16);
            float r2h = a2h - __uint_as_float(p2 & 0xffff0000u);
            float r3l = a3l - __uint_as_float(p3 << 16);
            float r3h = a3h - __uint_as_float(p3 & 0xffff0000u);
            asm("cvt.rn.bf16x2.f32 %0, %1, %2;" : "=r"(Alo[k][0]) : "f"(r0h), "f"(r0l));
            asm("cvt.rn.bf16x2.f32 %0, %1, %2;" : "=r"(Alo[k][1]) : "f"(r1h), "f"(r1l));
            asm("cvt.rn.bf16x2.f32 %0, %1, %2;" : "=r"(Alo[k][2]) : "f"(r2h), "f"(r2l));
            asm("cvt.rn.bf16x2.f32 %0, %1, %2;" : "=r"(Alo[k][3]) : "f"(r3h), "f"(r3l));
        }
    }

    // ---- output ----
    #pragma unroll
    for (int d = 0; d < 8; d++) {
        const int c0 = 8 * d + 2 * t4;
        *reinterpret_cast<float2*>(&out[(size_t)seqA * HS_DIM + c0]) =
            make_float2(hA[2 * d], hA[2 * d + 1]);
        *reinterpret_cast<float2*>(&out[(size_t)seqB * HS_DIM + c0]) =
            make_float2(hB[2 * d], hB[2 * d + 1]);
    }
}

extern "C" void kernel_launch(void* const* d_in, const int* in_sizes, int n_in,
                              void* d_out, int out_size)
{
    const int*   x    = (const int*)  d_in[0];
    const float* emb  = (const float*)d_in[1];
    const float* w_ih = (const float*)d_in[2];
    const float* w_hh = (const float*)d_in[3];
    const float* b_ih = (const float*)d_in[4];
    const float* b_hh = (const float*)d_in[5];
    float*       out  = (float*)d_out;

    cudaFuncSetAttribute(gru_mma, cudaFuncAttributeMaxDynamicSharedMemorySize, SMEM_SZ);

    zero_kernel<<<1, 1024>>>();
    len_pre_kernel<<<LEN_CTAS + (VOCAB + P_ROWS_PER_CTA - 1) / P_ROWS_PER_CTA, 256>>>(
        x, emb, w_ih, b_ih, b_hh);
    scan_scatter_kernel<<<1, 256>>>();
    gru_mma<<<NGROUP / 4, 128, SMEM_SZ>>>(x, w_hh, b_hh, out);
}

// round 15
// speedup vs baseline: 1.6396x; 1.6396x over previous
#include <cuda_runtime.h>
#include <cuda_bf16.h>
#include <cstdint>

// GRU sequence encoder, round 15: HMMA recurrence.
// R13 big-batch ILP + no spills (half-batches, 48 acc regs) + ldmatrix.x4
// (half the B loads) + tanh.approx sigmoids (MUFU 6->4 per dim).
// N=16384, L=512, ES=32, HS=64, gates [r|z|n] (torch order).
// Warp-autonomous: each warp owns 16 length-sorted seqs; no CTA sync in loop.

#define N_SEQ   16384
#define L_SEQ   512
#define ES_DIM  32
#define HS_DIM  64
#define G3      192
#define NGROUP  (N_SEQ / 16)   // 1024
#define NBUCKET 513
#define VOCAB   32000
#define WROW    72             // padded bf16 row stride (144 B)

__device__ float P[(size_t)VOCAB * G3];   // e.w_ih^T + b_ih (+b_hh for r,z)
__device__ int d_len[N_SEQ];
__device__ int d_bucket[NBUCKET];
__device__ int d_off[NBUCKET];
__device__ int d_sorted[N_SEQ];

// ---------------- PTX helpers ----------------

__device__ __forceinline__ uint32_t smem_to_u32(const void* p) {
    uint32_t a;
    asm("{ .reg .u64 t; cvta.to.shared.u64 t, %1; cvt.u32.u64 %0, t; }"
        : "=r"(a) : "l"(p));
    return a;
}

#define LDSM_X4(r, addr) \
    asm volatile("ldmatrix.sync.aligned.m8n8.x4.shared.b16 {%0,%1,%2,%3}, [%4];" \
                 : "=r"((r)[0]), "=r"((r)[1]), "=r"((r)[2]), "=r"((r)[3]) \
                 : "r"(addr))

#define MMA_BF16(c, a, b) \
    asm volatile("mma.sync.aligned.m16n8k16.row.col.f32.bf16.bf16.f32 " \
                 "{%0,%1,%2,%3}, {%4,%5,%6,%7}, {%8,%9}, {%0,%1,%2,%3};" \
                 : "+f"((c)[0]), "+f"((c)[1]), "+f"((c)[2]), "+f"((c)[3]) \
                 : "r"((a)[0]), "r"((a)[1]), "r"((a)[2]), "r"((a)[3]), \
                   "r"((b)[0]), "r"((b)[1]))

__device__ __forceinline__ float sigmoid_apx(float x) {
    float t;
    float y = 0.5f * x;
    asm("tanh.approx.f32 %0, %1;" : "=f"(t) : "f"(y));
    return fmaf(0.5f, t, 0.5f);
}

// one n-tile (8 gate rows): 12 HMMA, B via 4x ldmatrix.x4
__device__ __forceinline__ void mma_ntile(float acc[4],
                                          uint32_t addr_hi, uint32_t addr_lo,
                                          const uint32_t Ahi[4][4],
                                          const uint32_t Alo[4][4])
{
    uint32_t bh[8], bl[8];
    LDSM_X4(&bh[0], addr_hi);        // k 0..31  (tiles k0,k8,k16,k24)
    LDSM_X4(&bh[4], addr_hi + 64);   // k 32..63
    LDSM_X4(&bl[0], addr_lo);
    LDSM_X4(&bl[4], addr_lo + 64);
    #pragma unroll
    for (int k = 0; k < 4; k++) MMA_BF16(acc, Ahi[k], &bh[2 * k]);
    #pragma unroll
    for (int k = 0; k < 4; k++) MMA_BF16(acc, Alo[k], &bh[2 * k]);
    #pragma unroll
    for (int k = 0; k < 4; k++) MMA_BF16(acc, Ahi[k], &bl[2 * k]);
}

// ---------------- prepass ----------------

__global__ void zero_kernel() {
    int t = threadIdx.x;
    if (t < NBUCKET) d_bucket[t] = 0;
}

#define LEN_CTAS 2048
#define P_ROWS_PER_CTA 64

__global__ void len_pre_kernel(const int* __restrict__ x,
                               const float* __restrict__ emb,
                               const float* __restrict__ w_ih,
                               const float* __restrict__ b_ih,
                               const float* __restrict__ b_hh)
{
    if (blockIdx.x < LEN_CTAS) {
        int seq  = blockIdx.x * 8 + (threadIdx.x >> 5);
        int lane = threadIdx.x & 31;
        const int4* row = reinterpret_cast<const int4*>(x + (long)seq * L_SEQ);
        int c = 0;
        #pragma unroll
        for (int k = 0; k < 4; k++) {
            int4 v = row[lane + 32 * k];
            c += (v.x != 0) + (v.y != 0) + (v.z != 0) + (v.w != 0);
        }
        #pragma unroll
        for (int off = 16; off > 0; off >>= 1) c += __shfl_xor_sync(~0u, c, off);
        if (lane == 0) {
            d_len[seq] = c;
            atomicAdd(&d_bucket[c], 1);
        }
    } else {
        int j = threadIdx.x;
        if (j >= G3) return;
        float w[ES_DIM];
        {
            const float4* wr = reinterpret_cast<const float4*>(w_ih + (long)j * ES_DIM);
            #pragma unroll
            for (int k = 0; k < ES_DIM / 4; k++) {
                float4 v = wr[k];
                w[4*k+0] = v.x; w[4*k+1] = v.y; w[4*k+2] = v.z; w[4*k+3] = v.w;
            }
        }
        const float bj = b_ih[j] + ((j < 128) ? b_hh[j] : 0.0f);
        int v0 = (blockIdx.x - LEN_CTAS) * P_ROWS_PER_CTA;
        for (int v = v0; v < v0 + P_ROWS_PER_CTA && v < VOCAB; v++) {
            const float4* er = reinterpret_cast<const float4*>(emb + (long)v * ES_DIM);
            float acc = bj;
            #pragma unroll
            for (int k = 0; k < ES_DIM / 4; k++) {
                float4 e = __ldg(&er[k]);
                acc = fmaf(w[4*k+0], e.x, acc);
                acc = fmaf(w[4*k+1], e.y, acc);
                acc = fmaf(w[4*k+2], e.z, acc);
                acc = fmaf(w[4*k+3], e.w, acc);
            }
            P[(size_t)v * G3 + j] = acc;
        }
    }
}

__global__ void scan_scatter_kernel() {
    __shared__ int sb[NBUCKET], so[NBUCKET];
    int t = threadIdx.x;
    for (int i = t; i < NBUCKET; i += blockDim.x) sb[i] = d_bucket[i];
    __syncthreads();
    if (t == 0) {
        int run = 0;
        for (int l = NBUCKET - 1; l >= 0; l--) { so[l] = run; run += sb[l]; }
    }
    __syncthreads();
    for (int i = t; i < NBUCKET; i += blockDim.x) d_off[i] = so[i];
    __syncthreads();
    for (int seq = t; seq < N_SEQ; seq += blockDim.x) {
        int l = d_len[seq];
        int pos = atomicAdd(&d_off[l], 1);
        d_sorted[pos] = seq;
    }
}

// ---------------- main ----------------

#define SMEM_SZ (2 * G3 * WROW * 2)   // 55296 B: w_hi + w_lo

__global__ void __launch_bounds__(128, 2)
gru_mma(const int* __restrict__ x, const float* __restrict__ w_hh,
        const float* __restrict__ b_hh, float* __restrict__ out)
{
    extern __shared__ __align__(16) char smem[];
    __nv_bfloat16* whi = reinterpret_cast<__nv_bfloat16*>(smem);
    __nv_bfloat16* wlo = whi + G3 * WROW;

    const int tid = threadIdx.x;

    for (int idx = tid; idx < G3 * HS_DIM; idx += 128) {
        int r = idx >> 6, k = idx & 63;
        float w = w_hh[(long)r * HS_DIM + k];
        __nv_bfloat16 hi = __float2bfloat16(w);
        whi[r * WROW + k] = hi;
        wlo[r * WROW + k] = __float2bfloat16(w - __bfloat162float(hi));
    }
    __syncthreads();

    const int wid  = tid >> 5;
    const int lane = tid & 31;
    const int grp  = blockIdx.x * 4 + wid;

    const int g  = lane >> 2;    // owns seqs g, g+8 of the group
    const int t4 = lane & 3;     // cols 2*t4, 2*t4+1 per 8-wide n-tile

    const int base = grp * 16;
    const int seqA = d_sorted[base + g];
    const int seqB = d_sorted[base + g + 8];
    const int lenA = d_len[seqA];
    const int lenB = d_len[seqB];
    const int maxlen = d_len[d_sorted[base]];   // descending sort

    const uint32_t whi_u = smem_to_u32(whi);
    const uint32_t wlo_u = smem_to_u32(wlo);
    // x4 per-lane address: lanes 0-7 tile(k+0), 8-15 (k+8), 16-23 (k+16), 24-31 (k+24)
    const uint32_t laddr = (uint32_t)((lane & 7) * (WROW * 2) + (lane >> 3) * 16);

    float hA[16], hB[16];
    uint32_t Ahi[4][4], Alo[4][4];
    #pragma unroll
    for (int i = 0; i < 16; i++) { hA[i] = 0.f; hB[i] = 0.f; }
    #pragma unroll
    for (int k = 0; k < 4; k++)
        #pragma unroll
        for (int i = 0; i < 4; i++) { Ahi[k][i] = 0u; Alo[k][i] = 0u; }

    const int* xA = x + (size_t)seqA * L_SEQ;
    const int* xB = x + (size_t)seqB * L_SEQ;
    int tokA = __ldg(xA);
    int tokB = __ldg(xB);

    for (int t = 0; t < maxlen; t++) {
        const int tn = (t + 1 < L_SEQ) ? t + 1 : t;
        const int tokA_n = __ldg(xA + tn);
        const int tokB_n = __ldg(xB + tn);

        const float* pA = P + (size_t)tokA * G3;
        const float* pB = P + (size_t)tokB * G3;
        const bool liveA = (t < lenA);
        const bool liveB = (t < lenB);

        // ---- two half-batches of 4 dim-tiles: 144 HMMA (12 chains) each ----
        #pragma unroll
        for (int half = 0; half < 2; half++) {
            float accR[4][4], accZ[4][4], accN[4][4];
            #pragma unroll
            for (int q = 0; q < 4; q++)
                #pragma unroll
                for (int i = 0; i < 4; i++) {
                    accR[q][i] = 0.f; accZ[q][i] = 0.f; accN[q][i] = 0.f;
                }

            #pragma unroll
            for (int q = 0; q < 4; q++) {
                const int d = 4 * half + q;
                uint32_t roR = (uint32_t)(8 * d) * (WROW * 2) + laddr;
                uint32_t roZ = (uint32_t)(64 + 8 * d) * (WROW * 2) + laddr;
                uint32_t roN = (uint32_t)(128 + 8 * d) * (WROW * 2) + laddr;
                mma_ntile(accR[q], whi_u + roR, wlo_u + roR, Ahi, Alo);
                mma_ntile(accZ[q], whi_u + roZ, wlo_u + roZ, Ahi, Alo);
                mma_ntile(accN[q], whi_u + roN, wlo_u + roN, Ahi, Alo);
            }

            // ---- epilogue for these 4 dim-tiles ----
            #pragma unroll
            for (int q = 0; q < 4; q++) {
                const int d = 4 * half + q;
                const int c0 = 8 * d + 2 * t4;
                float2 gxrA = __ldg(reinterpret_cast<const float2*>(pA + c0));
                float2 gxzA = __ldg(reinterpret_cast<const float2*>(pA + 64 + c0));
                float2 gxnA = __ldg(reinterpret_cast<const float2*>(pA + 128 + c0));
                float2 gxrB = __ldg(reinterpret_cast<const float2*>(pB + c0));
                float2 gxzB = __ldg(reinterpret_cast<const float2*>(pB + 64 + c0));
                float2 gxnB = __ldg(reinterpret_cast<const float2*>(pB + 128 + c0));
                float2 bnn  = __ldg(reinterpret_cast<const float2*>(b_hh + 128 + c0));

                #pragma unroll
                for (int i = 0; i < 2; i++) {
                    float bn = i ? bnn.y : bnn.x;

                    float prA = (i ? gxrA.y : gxrA.x) + accR[q][i];
                    float pzA = (i ? gxzA.y : gxzA.x) + accZ[q][i];
                    float xnA = (i ? gxnA.y : gxnA.x);
                    float hnA = accN[q][i] + bn;
                    float rA = sigmoid_apx(prA);
                    float zA = sigmoid_apx(pzA);
                    float aA = fmaf(rA, hnA, xnA);
                    float nA = 1.0f - __fdividef(2.0f, __expf(2.0f * aA) + 1.0f);
                    float hoA = hA[2 * d + i];
                    hA[2 * d + i] = liveA ? fmaf(zA, hoA - nA, nA) : hoA;

                    float prB = (i ? gxrB.y : gxrB.x) + accR[q][2 + i];
                    float pzB = (i ? gxzB.y : gxzB.x) + accZ[q][2 + i];
                    float xnB = (i ? gxnB.y : gxnB.x);
                    float hnB = accN[q][2 + i] + bn;
                    float rB = sigmoid_apx(prB);
                    float zB = sigmoid_apx(pzB);
                    float aB = fmaf(rB, hnB, xnB);
                    float nB = 1.0f - __fdividef(2.0f, __expf(2.0f * aB) + 1.0f);
                    float hoB = hB[2 * d + i];
                    hB[2 * d + i] = liveB ? fmaf(zB, hoB - nB, nB) : hoB;
                }
            }
        }
        tokA = tokA_n;
        tokB = tokB_n;

        // ---- repack h into next step's A fragments (registers only) ----
        #pragma unroll
        for (int k = 0; k < 4; k++) {
            float a0l = hA[4 * k],     a0h = hA[4 * k + 1];
            float a1l = hB[4 * k],     a1h = hB[4 * k + 1];
            float a2l = hA[4 * k + 2], a2h = hA[4 * k + 3];
            float a3l = hB[4 * k + 2], a3h = hB[4 * k + 3];
            uint32_t p0, p1, p2, p3;
            asm("cvt.rn.bf16x2.f32 %0, %1, %2;" : "=r"(p0) : "f"(a0h), "f"(a0l));
            asm("cvt.rn.bf16x2.f32 %0, %1, %2;" : "=r"(p1) : "f"(a1h), "f"(a1l));
            asm("cvt.rn.bf16x2.f32 %0, %1, %2;" : "=r"(p2) : "f"(a2h), "f"(a2l));
            asm("cvt.rn.bf16x2.f32 %0, %1, %2;" : "=r"(p3) : "f"(a3h), "f"(a3l));
            Ahi[k][0] = p0; Ahi[k][1] = p1; Ahi[k][2] = p2; Ahi[k][3] = p3;
            float r0l = a0l - __uint_as_float(p0 << 16);
            float r0h = a0h - __uint_as_float(p0 & 0xffff0000u);
            float r1l = a1l - __uint_as_float(p1 << 16);
            float r1h = a1h - __uint_as_float(p1 & 0xffff0000u);
            float r2l = a2l - __uint_as_float(p2 << 16);
            float r2h = a2h - __uint_as_float(p2 & 0xffff0000u);
            float r3l = a3l - __uint_as_float(p3 << 16);
            float r3h = a3h - __uint_as_float(p3 & 0xffff0000u);
            asm("cvt.rn.bf16x2.f32 %0, %1, %2;" : "=r"(Alo[k][0]) : "f"(r0h), "f"(r0l));
            asm("cvt.rn.bf16x2.f32 %0, %1, %2;" : "=r"(Alo[k][1]) : "f"(r1h), "f"(r1l));
            asm("cvt.rn.bf16x2.f32 %0, %1, %2;" : "=r"(Alo[k][2]) : "f"(r2h), "f"(r2l));
            asm("cvt.rn.bf16x2.f32 %0, %1, %2;" : "=r"(Alo[k][3]) : "f"(r3h), "f"(r3l));
        }
    }

    // ---- output ----
    #pragma unroll
    for (int d = 0; d < 8; d++) {
        const int c0 = 8 * d + 2 * t4;
        *reinterpret_cast<float2*>(&out[(size_t)seqA * HS_DIM + c0]) =
            make_float2(hA[2 * d], hA[2 * d + 1]);
        *reinterpret_cast<float2*>(&out[(size_t)seqB * HS_DIM + c0]) =
            make_float2(hB[2 * d], hB[2 * d + 1]);
    }
}

extern "C" void kernel_launch(void* const* d_in, const int* in_sizes, int n_in,
                              void* d_out, int out_size)
{
    const int*   x    = (const int*)  d_in[0];
    const float* emb  = (const float*)d_in[1];
    const float* w_ih = (const float*)d_in[2];
    const float* w_hh = (const float*)d_in[3];
    const float* b_ih = (const float*)d_in[4];
    const float* b_hh = (const float*)d_in[5];
    float*       out  = (float*)d_out;

    cudaFuncSetAttribute(gru_mma, cudaFuncAttributeMaxDynamicSharedMemorySize, SMEM_SZ);

    zero_kernel<<<1, 1024>>>();
    len_pre_kernel<<<LEN_CTAS + (VOCAB + P_ROWS_PER_CTA - 1) / P_ROWS_PER_CTA, 256>>>(
        x, emb, w_ih, b_ih, b_hh);
    scan_scatter_kernel<<<1, 256>>>();
    gru_mma<<<NGROUP / 4, 128, SMEM_SZ>>>(x, w_hh, b_hh, out);
}

// round 17
// speedup vs baseline: 1.7164x; 1.0469x over previous
#include <cuda_runtime.h>
#include <cuda_bf16.h>
#include <cstdint>

// GRU sequence encoder, round 16: HMMA recurrence, warp-PAIR per group.
// N=16384, L=512, ES=32, HS=64, gates [r|z|n] (torch order).
//
// 2048 warps: pair (2p,2p+1) owns 16 length-sorted seqs; warp `half`
// computes dims [32*half,32*half+32) = 12 n-tiles = 144 HMMA m16n8k16
// (bf16 split precision, 3 terms) + epilogue for its dims. New h is
// exchanged in A-fragment form via smem (4x uint4/thread) with ONE
// 64-thread named barrier per step (double-buffered by parity).

#define N_SEQ   16384
#define L_SEQ   512
#define ES_DIM  32
#define HS_DIM  64
#define G3      192
#define NGROUP  (N_SEQ / 16)   // 1024
#define NBUCKET 513
#define VOCAB   32000
#define WROW    72             // padded bf16 row stride (144 B)

__device__ float P[(size_t)VOCAB * G3];   // e.w_ih^T + b_ih (+b_hh for r,z)
__device__ int d_len[N_SEQ];
__device__ int d_bucket[NBUCKET];
__device__ int d_off[NBUCKET];
__device__ int d_sorted[N_SEQ];

// ---------------- PTX helpers ----------------

__device__ __forceinline__ uint32_t smem_to_u32(const void* p) {
    uint32_t a;
    asm("{ .reg .u64 t; cvta.to.shared.u64 t, %1; cvt.u32.u64 %0, t; }"
        : "=r"(a) : "l"(p));
    return a;
}

#define LDSM_X4(r, addr) \
    asm volatile("ldmatrix.sync.aligned.m8n8.x4.shared.b16 {%0,%1,%2,%3}, [%4];" \
                 : "=r"((r)[0]), "=r"((r)[1]), "=r"((r)[2]), "=r"((r)[3]) \
                 : "r"(addr))

#define MMA_BF16(c, a, b) \
    asm volatile("mma.sync.aligned.m16n8k16.row.col.f32.bf16.bf16.f32 " \
                 "{%0,%1,%2,%3}, {%4,%5,%6,%7}, {%8,%9}, {%0,%1,%2,%3};" \
                 : "+f"((c)[0]), "+f"((c)[1]), "+f"((c)[2]), "+f"((c)[3]) \
                 : "r"((a)[0]), "r"((a)[1]), "r"((a)[2]), "r"((a)[3]), \
                   "r"((b)[0]), "r"((b)[1]))

#define BAR_PAIR(id) \
    asm volatile("bar.sync %0, 64;" :: "r"(id) : "memory")

__device__ __forceinline__ float sigmoid_apx(float x) {
    float t;
    float y = 0.5f * x;
    asm("tanh.approx.f32 %0, %1;" : "=f"(t) : "f"(y));
    return fmaf(0.5f, t, 0.5f);
}

// one n-tile (8 gate rows): 12 HMMA, B via 4x ldmatrix.x4
__device__ __forceinline__ void mma_ntile(float acc[4],
                                          uint32_t addr_hi, uint32_t addr_lo,
                                          const uint32_t Ahi[4][4],
                                          const uint32_t Alo[4][4])
{
    uint32_t bh[8], bl[8];
    LDSM_X4(&bh[0], addr_hi);        // k 0..31
    LDSM_X4(&bh[4], addr_hi + 64);   // k 32..63
    LDSM_X4(&bl[0], addr_lo);
    LDSM_X4(&bl[4], addr_lo + 64);
    #pragma unroll
    for (int k = 0; k < 4; k++) MMA_BF16(acc, Ahi[k], &bh[2 * k]);
    #pragma unroll
    for (int k = 0; k < 4; k++) MMA_BF16(acc, Alo[k], &bh[2 * k]);
    #pragma unroll
    for (int k = 0; k < 4; k++) MMA_BF16(acc, Ahi[k], &bl[2 * k]);
}

// ---------------- prepass ----------------

__global__ void zero_kernel() {
    int t = threadIdx.x;
    if (t < NBUCKET) d_bucket[t] = 0;
}

#define LEN_CTAS 2048
#define P_ROWS_PER_CTA 64

__global__ void len_pre_kernel(const int* __restrict__ x,
                               const float* __restrict__ emb,
                               const float* __restrict__ w_ih,
                               const float* __restrict__ b_ih,
                               const float* __restrict__ b_hh)
{
    if (blockIdx.x < LEN_CTAS) {
        int seq  = blockIdx.x * 8 + (threadIdx.x >> 5);
        int lane = threadIdx.x & 31;
        const int4* row = reinterpret_cast<const int4*>(x + (long)seq * L_SEQ);
        int c = 0;
        #pragma unroll
        for (int k = 0; k < 4; k++) {
            int4 v = row[lane + 32 * k];
            c += (v.x != 0) + (v.y != 0) + (v.z != 0) + (v.w != 0);
        }
        #pragma unroll
        for (int off = 16; off > 0; off >>= 1) c += __shfl_xor_sync(~0u, c, off);
        if (lane == 0) {
            d_len[seq] = c;
            atomicAdd(&d_bucket[c], 1);
        }
    } else {
        int j = threadIdx.x;
        if (j >= G3) return;
        float w[ES_DIM];
        {
            const float4* wr = reinterpret_cast<const float4*>(w_ih + (long)j * ES_DIM);
            #pragma unroll
            for (int k = 0; k < ES_DIM / 4; k++) {
                float4 v = wr[k];
                w[4*k+0] = v.x; w[4*k+1] = v.y; w[4*k+2] = v.z; w[4*k+3] = v.w;
            }
        }
        const float bj = b_ih[j] + ((j < 128) ? b_hh[j] : 0.0f);
        int v0 = (blockIdx.x - LEN_CTAS) * P_ROWS_PER_CTA;
        for (int v = v0; v < v0 + P_ROWS_PER_CTA && v < VOCAB; v++) {
            const float4* er = reinterpret_cast<const float4*>(emb + (long)v * ES_DIM);
            float acc = bj;
            #pragma unroll
            for (int k = 0; k < ES_DIM / 4; k++) {
                float4 e = __ldg(&er[k]);
                acc = fmaf(w[4*k+0], e.x, acc);
                acc = fmaf(w[4*k+1], e.y, acc);
                acc = fmaf(w[4*k+2], e.z, acc);
                acc = fmaf(w[4*k+3], e.w, acc);
            }
            P[(size_t)v * G3 + j] = acc;
        }
    }
}

__global__ void scan_scatter_kernel() {
    __shared__ int sb[NBUCKET], so[NBUCKET];
    int t = threadIdx.x;
    for (int i = t; i < NBUCKET; i += blockDim.x) sb[i] = d_bucket[i];
    __syncthreads();
    if (t == 0) {
        int run = 0;
        for (int l = NBUCKET - 1; l >= 0; l--) { so[l] = run; run += sb[l]; }
    }
    __syncthreads();
    for (int i = t; i < NBUCKET; i += blockDim.x) d_off[i] = so[i];
    __syncthreads();
    for (int seq = t; seq < N_SEQ; seq += blockDim.x) {
        int l = d_len[seq];
        int pos = atomicAdd(&d_off[l], 1);
        d_sorted[pos] = seq;
    }
}

// ---------------- main ----------------

#define SMEM_W (2 * G3 * WROW * 2)   // 55296 B (dynamic): w_hi + w_lo

__global__ void __launch_bounds__(256, 2)
gru_mma(const int* __restrict__ x, const float* __restrict__ w_hh,
        const float* __restrict__ b_hh, float* __restrict__ out)
{
    extern __shared__ __align__(16) char smem[];
    __nv_bfloat16* whi = reinterpret_cast<__nv_bfloat16*>(smem);
    __nv_bfloat16* wlo = whi + G3 * WROW;
    // exchange: [parity][pair][half][vec][lane]
    __shared__ uint4 exch[2][4][2][4][32];

    const int tid = threadIdx.x;

    for (int idx = tid; idx < G3 * HS_DIM; idx += 256) {
        int r = idx >> 6, k = idx & 63;
        float w = w_hh[(long)r * HS_DIM + k];
        __nv_bfloat16 hi = __float2bfloat16(w);
        whi[r * WROW + k] = hi;
        wlo[r * WROW + k] = __float2bfloat16(w - __bfloat162float(hi));
    }
    __syncthreads();

    const int wid  = tid >> 5;
    const int lane = tid & 31;
    const int pair = wid >> 1;                 // 0..3
    const int half = wid & 1;                  // dims [32*half, 32*half+32)
    const int grp  = blockIdx.x * 4 + pair;

    const int g  = lane >> 2;
    const int t4 = lane & 3;

    const int base = grp * 16;
    const int seqA = d_sorted[base + g];
    const int seqB = d_sorted[base + g + 8];
    const int lenA = d_len[seqA];
    const int lenB = d_len[seqB];
    const int maxlen = d_len[d_sorted[base]];   // descending sort

    const uint32_t whi_u = smem_to_u32(whi);
    const uint32_t wlo_u = smem_to_u32(wlo);
    const uint32_t laddr = (uint32_t)((lane & 7) * (WROW * 2) + (lane >> 3) * 16);

    // this warp's 8 dims per thread (2 seqs): hA/hB[2q+i] = dim 8*(4*half+q)+2*t4+i
    float hA[8], hB[8];
    uint32_t Ahi[4][4], Alo[4][4];
    #pragma unroll
    for (int i = 0; i < 8; i++) { hA[i] = 0.f; hB[i] = 0.f; }
    #pragma unroll
    for (int k = 0; k < 4; k++)
        #pragma unroll
        for (int i = 0; i < 4; i++) { Ahi[k][i] = 0u; Alo[k][i] = 0u; }

    const int* xA = x + (size_t)seqA * L_SEQ;
    const int* xB = x + (size_t)seqB * L_SEQ;
    int tokA = __ldg(xA);
    int tokB = __ldg(xB);

    const int kme = 2 * half;        // my A k-tiles: kme, kme+1
    const int kot = 2 * (1 - half);  // partner's

    for (int t = 0; t < maxlen; t++) {
        const int tn = (t + 1 < L_SEQ) ? t + 1 : t;
        const int tokA_n = __ldg(xA + tn);
        const int tokB_n = __ldg(xB + tn);

        const float* pA = P + (size_t)tokA * G3;
        const float* pB = P + (size_t)tokB * G3;
        const bool liveA = (t < lenA);
        const bool liveB = (t < lenB);

        // ---- 12 n-tiles (my 4 dim-tiles x 3 gates): 144 HMMA, 12 chains ----
        float accR[4][4], accZ[4][4], accN[4][4];
        #pragma unroll
        for (int q = 0; q < 4; q++)
            #pragma unroll
            for (int i = 0; i < 4; i++) {
                accR[q][i] = 0.f; accZ[q][i] = 0.f; accN[q][i] = 0.f;
            }
        #pragma unroll
        for (int q = 0; q < 4; q++) {
            const int d = 4 * half + q;
            uint32_t roR = (uint32_t)(8 * d) * (WROW * 2) + laddr;
            uint32_t roZ = (uint32_t)(64 + 8 * d) * (WROW * 2) + laddr;
            uint32_t roN = (uint32_t)(128 + 8 * d) * (WROW * 2) + laddr;
            mma_ntile(accR[q], whi_u + roR, wlo_u + roR, Ahi, Alo);
            mma_ntile(accZ[q], whi_u + roZ, wlo_u + roZ, Ahi, Alo);
            mma_ntile(accN[q], whi_u + roN, wlo_u + roN, Ahi, Alo);
        }

        // ---- epilogue for my 4 dim-tiles ----
        #pragma unroll
        for (int q = 0; q < 4; q++) {
            const int d = 4 * half + q;
            const int c0 = 8 * d + 2 * t4;
            float2 gxrA = __ldg(reinterpret_cast<const float2*>(pA + c0));
            float2 gxzA = __ldg(reinterpret_cast<const float2*>(pA + 64 + c0));
            float2 gxnA = __ldg(reinterpret_cast<const float2*>(pA + 128 + c0));
            float2 gxrB = __ldg(reinterpret_cast<const float2*>(pB + c0));
            float2 gxzB = __ldg(reinterpret_cast<const float2*>(pB + 64 + c0));
            float2 gxnB = __ldg(reinterpret_cast<const float2*>(pB + 128 + c0));
            float2 bnn  = __ldg(reinterpret_cast<const float2*>(b_hh + 128 + c0));

            #pragma unroll
            for (int i = 0; i < 2; i++) {
                float bn = i ? bnn.y : bnn.x;

                float prA = (i ? gxrA.y : gxrA.x) + accR[q][i];
                float pzA = (i ? gxzA.y : gxzA.x) + accZ[q][i];
                float xnA = (i ? gxnA.y : gxnA.x);
                float hnA = accN[q][i] + bn;
                float rA = sigmoid_apx(prA);
                float zA = sigmoid_apx(pzA);
                float aA = fmaf(rA, hnA, xnA);
                float nA = 1.0f - __fdividef(2.0f, __expf(2.0f * aA) + 1.0f);
                float hoA = hA[2 * q + i];
                hA[2 * q + i] = liveA ? fmaf(zA, hoA - nA, nA) : hoA;

                float prB = (i ? gxrB.y : gxrB.x) + accR[q][2 + i];
                float pzB = (i ? gxzB.y : gxzB.x) + accZ[q][2 + i];
                float xnB = (i ? gxnB.y : gxnB.x);
                float hnB = accN[q][2 + i] + bn;
                float rB = sigmoid_apx(prB);
                float zB = sigmoid_apx(pzB);
                float aB = fmaf(rB, hnB, xnB);
                float nB = 1.0f - __fdividef(2.0f, __expf(2.0f * aB) + 1.0f);
                float hoB = hB[2 * q + i];
                hB[2 * q + i] = liveB ? fmaf(zB, hoB - nB, nB) : hoB;
            }
        }
        tokA = tokA_n;
        tokB = tokB_n;

        // ---- repack my half into A-fragment form (k-tiles kme, kme+1) ----
        #pragma unroll
        for (int kq = 0; kq < 2; kq++) {
            const int k = kme + kq;
            float a0l = hA[4 * kq],     a0h = hA[4 * kq + 1];
            float a1l = hB[4 * kq],     a1h = hB[4 * kq + 1];
            float a2l = hA[4 * kq + 2], a2h = hA[4 * kq + 3];
            float a3l = hB[4 * kq + 2], a3h = hB[4 * kq + 3];
            uint32_t p0, p1, p2, p3;
            asm("cvt.rn.bf16x2.f32 %0, %1, %2;" : "=r"(p0) : "f"(a0h), "f"(a0l));
            asm("cvt.rn.bf16x2.f32 %0, %1, %2;" : "=r"(p1) : "f"(a1h), "f"(a1l));
            asm("cvt.rn.bf16x2.f32 %0, %1, %2;" : "=r"(p2) : "f"(a2h), "f"(a2l));
            asm("cvt.rn.bf16x2.f32 %0, %1, %2;" : "=r"(p3) : "f"(a3h), "f"(a3l));
            Ahi[k][0] = p0; Ahi[k][1] = p1; Ahi[k][2] = p2; Ahi[k][3] = p3;
            float r0l = a0l - __uint_as_float(p0 << 16);
            float r0h = a0h - __uint_as_float(p0 & 0xffff0000u);
            float r1l = a1l - __uint_as_float(p1 << 16);
            float r1h = a1h - __uint_as_float(p1 & 0xffff0000u);
            float r2l = a2l - __uint_as_float(p2 << 16);
            float r2h = a2h - __uint_as_float(p2 & 0xffff0000u);
            float r3l = a3l - __uint_as_float(p3 << 16);
            float r3h = a3h - __uint_as_float(p3 & 0xffff0000u);
            asm("cvt.rn.bf16x2.f32 %0, %1, %2;" : "=r"(Alo[k][0]) : "f"(r0h), "f"(r0l));
            asm("cvt.rn.bf16x2.f32 %0, %1, %2;" : "=r"(Alo[k][1]) : "f"(r1h), "f"(r1l));
            asm("cvt.rn.bf16x2.f32 %0, %1, %2;" : "=r"(Alo[k][2]) : "f"(r2h), "f"(r2l));
            asm("cvt.rn.bf16x2.f32 %0, %1, %2;" : "=r"(Alo[k][3]) : "f"(r3h), "f"(r3l));
        }

        // ---- exchange with partner warp (one named barrier) ----
        const int pb = t & 1;
        exch[pb][pair][half][0][lane] =
            make_uint4(Ahi[kme][0], Ahi[kme][1], Ahi[kme][2], Ahi[kme][3]);
        exch[pb][pair][half][1][lane] =
            make_uint4(Ahi[kme + 1][0], Ahi[kme + 1][1], Ahi[kme + 1][2], Ahi[kme + 1][3]);
        exch[pb][pair][half][2][lane] =
            make_uint4(Alo[kme][0], Alo[kme][1], Alo[kme][2], Alo[kme][3]);
        exch[pb][pair][half][3][lane] =
            make_uint4(Alo[kme + 1][0], Alo[kme + 1][1], Alo[kme + 1][2], Alo[kme + 1][3]);
        BAR_PAIR(pair);
        {
            uint4 v0 = exch[pb][pair][1 - half][0][lane];
            uint4 v1 = exch[pb][pair][1 - half][1][lane];
            uint4 v2 = exch[pb][pair][1 - half][2][lane];
            uint4 v3 = exch[pb][pair][1 - half][3][lane];
            Ahi[kot][0] = v0.x; Ahi[kot][1] = v0.y; Ahi[kot][2] = v0.z; Ahi[kot][3] = v0.w;
            Ahi[kot + 1][0] = v1.x; Ahi[kot + 1][1] = v1.y; Ahi[kot + 1][2] = v1.z; Ahi[kot + 1][3] = v1.w;
            Alo[kot][0] = v2.x; Alo[kot][1] = v2.y; Alo[kot][2] = v2.z; Alo[kot][3] = v2.w;
            Alo[kot + 1][0] = v3.x; Alo[kot + 1][1] = v3.y; Alo[kot + 1][2] = v3.z; Alo[kot + 1][3] = v3.w;
        }
    }

    // ---- output: my 32 dims for the 16 seqs ----
    #pragma unroll
    for (int q = 0; q < 4; q++) {
        const int c0 = 8 * (4 * half + q) + 2 * t4;
        *reinterpret_cast<float2*>(&out[(size_t)seqA * HS_DIM + c0]) =
            make_float2(hA[2 * q], hA[2 * q + 1]);
        *reinterpret_cast<float2*>(&out[(size_t)seqB * HS_DIM + c0]) =
            make_float2(hB[2 * q], hB[2 * q + 1]);
    }
}

extern "C" void kernel_launch(void* const* d_in, const int* in_sizes, int n_in,
                              void* d_out, int out_size)
{
    const int*   x    = (const int*)  d_in[0];
    const float* emb  = (const float*)d_in[1];
    const float* w_ih = (const float*)d_in[2];
    const float* w_hh = (const float*)d_in[3];
    const float* b_ih = (const float*)d_in[4];
    const float* b_hh = (const float*)d_in[5];
    float*       out  = (float*)d_out;

    cudaFuncSetAttribute(gru_mma, cudaFuncAttributeMaxDynamicSharedMemorySize, SMEM_W);

    zero_kernel<<<1, 1024>>>();
    len_pre_kernel<<<LEN_CTAS + (VOCAB + P_ROWS_PER_CTA - 1) / P_ROWS_PER_CTA, 256>>>(
        x, emb, w_ih, b_ih, b_hh);
    scan_scatter_kernel<<<1, 256>>>();
    gru_mma<<<NGROUP / 4, 256, SMEM_W>>>(x, w_hh, b_hh, out);
}